// round 8
// baseline (speedup 1.0000x reference)
#include <cuda_runtime.h>
#include <cstdint>

#define SS   2048
#define DD   1024
#define NH   16
#define HDIM 64
#define NBINS 8192
#define CCAP  32768
#define RANK0 3984587

#define BM 128
#define BN 128
#define BK 16
#define TM 8
#define TN 8

// ---------------- scratch ----------------
__device__ float g_q[SS * DD];
__device__ float g_k[SS * DD];
__device__ float g_v[SS * DD];
__device__ float g_o[SS * DD];
__device__ float g_scores[(size_t)NH * SS * SS];   // 256 MB
__device__ unsigned g_hist[NH * NBINS];
__device__ float g_cand[NH * CCAP];
__device__ int g_cnt[NH];
__device__ int g_b0[NH], g_b1[NH], g_base[NH];
__device__ float g_thr[NH];

__device__ __forceinline__ float inf_f() { return __int_as_float(0x7f800000); }

__device__ __forceinline__ int score_bin(float v) {
    int b = __float2int_rd((v + 16.0f) * 256.0f);   // 8192 bins over [-16,16)
    return min(max(b, 0), NBINS - 1);
}

// ---------------- K0: zero per-launch state ----------------
__global__ void zero_kernel() {
    int i = blockIdx.x * blockDim.x + threadIdx.x;
    if (i < NH * NBINS) g_hist[i] = 0;
    if (i < NH) g_cnt[i] = 0;
}

// ================= fp32 SIMT GEMM (mask-critical path: q, k, scores) =========
template<int KTOT, bool BT>
__device__ __forceinline__ void gemm_mainloop(
    const float* __restrict__ A, int lda,
    const float* __restrict__ Bm, int ldb,
    int bm, int bn, float acc[TM][TN])
{
    __shared__ float As[2][BK][BM];
    __shared__ float Bs[2][BK][BN];
    const int tid = threadIdx.x;
    const int tr = (tid >> 4) * TM;
    const int tc = (tid & 15) * TN;

    const int ar0 = tid >> 2;           // 0..63
    const int ar1 = ar0 + 64;           // 64..127
    const int ac  = (tid & 3) * 4;      // 0,4,8,12
    const int br0 = tid >> 5;           // 0..7
    const int br1 = br0 + 8;
    const int bc  = (tid & 31) * 4;

    float4 pa0, pa1, pb0, pb1;

    auto loadT = [&](int k0) {
        pa0 = *(const float4*)&A[(size_t)(bm + ar0) * lda + k0 + ac];
        pa1 = *(const float4*)&A[(size_t)(bm + ar1) * lda + k0 + ac];
        if (BT) {
            pb0 = *(const float4*)&Bm[(size_t)(bn + ar0) * ldb + k0 + ac];
            pb1 = *(const float4*)&Bm[(size_t)(bn + ar1) * ldb + k0 + ac];
        } else {
            pb0 = *(const float4*)&Bm[(size_t)(k0 + br0) * ldb + bn + bc];
            pb1 = *(const float4*)&Bm[(size_t)(k0 + br1) * ldb + bn + bc];
        }
    };
    auto storeT = [&](int buf) {
        As[buf][ac + 0][ar0] = pa0.x; As[buf][ac + 1][ar0] = pa0.y;
        As[buf][ac + 2][ar0] = pa0.z; As[buf][ac + 3][ar0] = pa0.w;
        As[buf][ac + 0][ar1] = pa1.x; As[buf][ac + 1][ar1] = pa1.y;
        As[buf][ac + 2][ar1] = pa1.z; As[buf][ac + 3][ar1] = pa1.w;
        if (BT) {
            Bs[buf][ac + 0][ar0] = pb0.x; Bs[buf][ac + 1][ar0] = pb0.y;
            Bs[buf][ac + 2][ar0] = pb0.z; Bs[buf][ac + 3][ar0] = pb0.w;
            Bs[buf][ac + 0][ar1] = pb1.x; Bs[buf][ac + 1][ar1] = pb1.y;
            Bs[buf][ac + 2][ar1] = pb1.z; Bs[buf][ac + 3][ar1] = pb1.w;
        } else {
            *(float4*)&Bs[buf][br0][bc] = pb0;
            *(float4*)&Bs[buf][br1][bc] = pb1;
        }
    };

    loadT(0);
    storeT(0);
    __syncthreads();
    const int NIT = KTOT / BK;
    for (int it = 0; it < NIT; ++it) {
        int buf = it & 1;
        if (it + 1 < NIT) loadT((it + 1) * BK);
#pragma unroll
        for (int kk = 0; kk < BK; ++kk) {
            float4 a0 = *(const float4*)&As[buf][kk][tr];
            float4 a1 = *(const float4*)&As[buf][kk][tr + 4];
            float4 b0 = *(const float4*)&Bs[buf][kk][tc];
            float4 b1 = *(const float4*)&Bs[buf][kk][tc + 4];
            float af[TM] = {a0.x, a0.y, a0.z, a0.w, a1.x, a1.y, a1.z, a1.w};
            float bf[TN] = {b0.x, b0.y, b0.z, b0.w, b1.x, b1.y, b1.z, b1.w};
#pragma unroll
            for (int i = 0; i < TM; i++)
#pragma unroll
                for (int j = 0; j < TN; j++)
                    acc[i][j] += af[i] * bf[j];
        }
        if (it + 1 < NIT) storeT(buf ^ 1);
        __syncthreads();
    }
}

// ---------------- K1: q,k projections (fp32, mask-critical) ----------------
__global__ __launch_bounds__(256, 2) void qk_kernel(
    const float* __restrict__ x,
    const float* __restrict__ Wq, const float* __restrict__ bq,
    const float* __restrict__ Wk, const float* __restrict__ bk,
    float* __restrict__ q, float* __restrict__ k)
{
    const float* W; const float* bias; float* C;
    if (blockIdx.z == 0) { W = Wq; bias = bq; C = q; }
    else                 { W = Wk; bias = bk; C = k; }

    int bm = blockIdx.y * BM, bn = blockIdx.x * BN;
    int tid = threadIdx.x;
    int tr = (tid >> 4) * TM, tc = (tid & 15) * TN;
    float acc[TM][TN] = {};
    gemm_mainloop<DD, false>(x, DD, W, DD, bm, bn, acc);
#pragma unroll
    for (int i = 0; i < TM; i++) {
        int row = bm + tr + i;
#pragma unroll
        for (int j = 0; j < TN; j += 4) {
            float4 r;
            r.x = acc[i][j + 0] + bias[bn + tc + j + 0];
            r.y = acc[i][j + 1] + bias[bn + tc + j + 1];
            r.z = acc[i][j + 2] + bias[bn + tc + j + 2];
            r.w = acc[i][j + 3] + bias[bn + tc + j + 3];
            *(float4*)&C[(size_t)row * DD + bn + tc + j] = r;
        }
    }
}

// ---------------- K2: scores = q_h @ k_h^T * 0.125, fused histogram (fp32) ----
__global__ __launch_bounds__(256, 2) void scores_kernel() {
    extern __shared__ unsigned shh[];   // NBINS -> 32 KB dynamic
    int h = blockIdx.z;
    int bm = blockIdx.y * BM, bn = blockIdx.x * BN;
    int tid = threadIdx.x;
    int tr = (tid >> 4) * TM, tc = (tid & 15) * TN;

    for (int i = tid; i < NBINS; i += 256) shh[i] = 0;

    float acc[TM][TN] = {};
    gemm_mainloop<HDIM, true>(g_q + h * HDIM, DD, g_k + h * HDIM, DD, bm, bn, acc);
    // mainloop ends with __syncthreads(): shh zeroing complete.

    float* out = g_scores + (size_t)h * SS * SS;
#pragma unroll
    for (int i = 0; i < TM; i++) {
        size_t row = bm + tr + i;
#pragma unroll
        for (int j = 0; j < TN; j += 4) {
            float4 r;
            r.x = acc[i][j + 0] * 0.125f;
            r.y = acc[i][j + 1] * 0.125f;
            r.z = acc[i][j + 2] * 0.125f;
            r.w = acc[i][j + 3] * 0.125f;
            *(float4*)&out[row * SS + bn + tc + j] = r;
            atomicAdd(&shh[score_bin(r.x)], 1u);
            atomicAdd(&shh[score_bin(r.y)], 1u);
            atomicAdd(&shh[score_bin(r.z)], 1u);
            atomicAdd(&shh[score_bin(r.w)], 1u);
        }
    }
    __syncthreads();
    unsigned* gh = g_hist + h * NBINS;
    for (int i = tid; i < NBINS; i += 256) {
        unsigned c = shh[i];
        if (c) atomicAdd(&gh[i], c);
    }
}

// ================= tf32x3 tensor-core GEMM (mask-safe path: v, outproj) =====
__device__ __forceinline__ float2 split_tf32(float x) {
    uint32_t h;
    asm("cvt.rna.tf32.f32 %0, %1;" : "=r"(h) : "f"(x));
    float hf = __uint_as_float(h);
    float r = x - hf;
    uint32_t l;
    asm("cvt.rna.tf32.f32 %0, %1;" : "=r"(l) : "f"(r));
    return make_float2(hf, __uint_as_float(l));
}

__device__ __forceinline__ void mma_tf32(float c[4],
    float a0, float a1, float a2, float a3, float b0, float b1)
{
    uint32_t A0 = __float_as_uint(a0), A1 = __float_as_uint(a1);
    uint32_t A2 = __float_as_uint(a2), A3 = __float_as_uint(a3);
    uint32_t B0 = __float_as_uint(b0), B1 = __float_as_uint(b1);
    asm volatile(
        "mma.sync.aligned.m16n8k8.row.col.f32.tf32.tf32.f32 "
        "{%0,%1,%2,%3},{%4,%5,%6,%7},{%8,%9},{%0,%1,%2,%3};"
        : "+f"(c[0]), "+f"(c[1]), "+f"(c[2]), "+f"(c[3])
        : "r"(A0), "r"(A1), "r"(A2), "r"(A3), "r"(B0), "r"(B1));
}

__device__ __forceinline__ int sw(int r, int c) { return r * 16 + (c ^ (r & 15)); }

// C[128,128] = A[128,K] @ B[K,128]; B row-major, transposed into smem.
template<int KTOT>
__device__ __forceinline__ void mma_mainloop_tf32(
    const float* __restrict__ A, int lda,
    const float* __restrict__ B, int ldb,
    int bm, int bn, float2* __restrict__ smem, float c[4][4][4])
{
    float2* sA = smem;
    float2* sB = smem + 4096;
    const int tid = threadIdx.x;
    const int lane = tid & 31;
    const int wid = tid >> 5;
    const int g = lane >> 2;
    const int t = lane & 3;
    const int wm = (wid >> 2) * 64;
    const int wn = (wid & 3) * 32;

    const int arow = tid >> 1;
    const int ac = (tid & 1) * 8;
    const int bk1 = tid >> 5;
    const int bnc = (tid & 31) * 4;

    float4 ra0, ra1, rb0, rb1;

    auto load_g = [&](int k0) {
        ra0 = *(const float4*)&A[(size_t)(bm + arow) * lda + k0 + ac];
        ra1 = *(const float4*)&A[(size_t)(bm + arow) * lda + k0 + ac + 4];
        rb0 = *(const float4*)&B[(size_t)(k0 + bk1) * ldb + bn + bnc];
        rb1 = *(const float4*)&B[(size_t)(k0 + bk1 + 8) * ldb + bn + bnc];
    };
    auto store_s = [&](int buf) {
        float2* dA = sA + buf * 2048;
        float2* dB = sB + buf * 2048;
        float va[8] = {ra0.x, ra0.y, ra0.z, ra0.w, ra1.x, ra1.y, ra1.z, ra1.w};
#pragma unroll
        for (int i = 0; i < 8; i++) dA[sw(arow, ac + i)] = split_tf32(va[i]);
        float vb0[4] = {rb0.x, rb0.y, rb0.z, rb0.w};
        float vb1[4] = {rb1.x, rb1.y, rb1.z, rb1.w};
#pragma unroll
        for (int j = 0; j < 4; j++) {
            dB[sw(bnc + j, bk1)]     = split_tf32(vb0[j]);
            dB[sw(bnc + j, bk1 + 8)] = split_tf32(vb1[j]);
        }
    };

    load_g(0);
    store_s(0);
    __syncthreads();
    const int NIT = KTOT / BK;
    for (int it = 0; it < NIT; ++it) {
        int buf = it & 1;
        if (it + 1 < NIT) load_g((it + 1) * BK);
        const float2* tA = sA + buf * 2048;
        const float2* tB = sB + buf * 2048;
#pragma unroll
        for (int ks = 0; ks < 2; ++ks) {
            int kc = ks * 8;
            float2 bf0[4], bf1[4];
#pragma unroll
            for (int nt = 0; nt < 4; nt++) {
                int nb = wn + nt * 8 + g;
                bf0[nt] = tB[sw(nb, kc + t)];
                bf1[nt] = tB[sw(nb, kc + t + 4)];
            }
#pragma unroll
            for (int mt = 0; mt < 4; mt++) {
                int mb = wm + mt * 16;
                float2 a0 = tA[sw(mb + g,     kc + t)];
                float2 a1 = tA[sw(mb + g + 8, kc + t)];
                float2 a2 = tA[sw(mb + g,     kc + t + 4)];
                float2 a3 = tA[sw(mb + g + 8, kc + t + 4)];
#pragma unroll
                for (int nt = 0; nt < 4; nt++) {
                    mma_tf32(c[mt][nt], a0.x, a1.x, a2.x, a3.x, bf0[nt].x, bf1[nt].x);
                    mma_tf32(c[mt][nt], a0.x, a1.x, a2.x, a3.x, bf0[nt].y, bf1[nt].y);
                    mma_tf32(c[mt][nt], a0.y, a1.y, a2.y, a3.y, bf0[nt].x, bf1[nt].x);
                }
            }
        }
        if (it + 1 < NIT) store_s(buf ^ 1);
        __syncthreads();
    }
}

// shared epilogue for tf32 GEMM + bias
__device__ __forceinline__ void tf32_epilogue(
    float c[4][4][4], const float* __restrict__ bias, float* __restrict__ C,
    int bm, int bn)
{
    int lane = threadIdx.x & 31, wid = threadIdx.x >> 5;
    int g = lane >> 2, t = lane & 3;
    int wm = (wid >> 2) * 64, wn = (wid & 3) * 32;
#pragma unroll
    for (int mt = 0; mt < 4; mt++) {
        int r0 = bm + wm + mt * 16 + g;
#pragma unroll
        for (int nt = 0; nt < 4; nt++) {
            int col = bn + wn + nt * 8 + 2 * t;
            float bx = bias[col], by = bias[col + 1];
            *(float2*)&C[(size_t)r0 * DD + col] =
                make_float2(c[mt][nt][0] + bx, c[mt][nt][1] + by);
            *(float2*)&C[(size_t)(r0 + 8) * DD + col] =
                make_float2(c[mt][nt][2] + bx, c[mt][nt][3] + by);
        }
    }
}

// ---------------- K1b: v projection (tf32x3; v never feeds the mask) ---------
__global__ __launch_bounds__(256, 2) void v_kernel(
    const float* __restrict__ x, const float* __restrict__ Wv,
    const float* __restrict__ bv, float* __restrict__ v)
{
    extern __shared__ float2 smem2[];
    int bm = blockIdx.y * 128, bn = blockIdx.x * 128;
    float c[4][4][4] = {};
    mma_mainloop_tf32<DD>(x, DD, Wv, DD, bm, bn, smem2, c);
    tf32_epilogue(c, bv, v, bm, bn);
}

// ---------------- K8: output projection (tf32x3; post-mask) -----------------
__global__ __launch_bounds__(256, 2) void outproj_kernel(
    const float* __restrict__ A, const float* __restrict__ W,
    const float* __restrict__ bias, float* __restrict__ C)
{
    extern __shared__ float2 smem2[];
    int bm = blockIdx.y * 128, bn = blockIdx.x * 128;
    float c[4][4][4] = {};
    mma_mainloop_tf32<DD>(A, DD, W, DD, bm, bn, smem2, c);
    tf32_epilogue(c, bias, C, bm, bn);
}

// ---------------- K4: find bins containing ranks RANK0, RANK0+1 ----------------
__global__ __launch_bounds__(256) void findbin_kernel() {
    int h = blockIdx.x;
    const unsigned* hh = g_hist + h * NBINS;
    int tid = threadIdx.x;
    const int PER = NBINS / 256;   // 32
    int start = tid * PER;
    unsigned s = 0;
#pragma unroll
    for (int i = 0; i < PER; i++) s += hh[start + i];
    unsigned x = s;
#pragma unroll
    for (int o = 1; o < 32; o <<= 1) {
        unsigned y = __shfl_up_sync(0xffffffffu, x, o);
        if ((tid & 31) >= o) x += y;
    }
    __shared__ unsigned wsum[8];
    if ((tid & 31) == 31) wsum[tid >> 5] = x;
    __syncthreads();
    if (tid == 0) {
        unsigned c = 0;
        for (int w = 0; w < 8; w++) { unsigned t2 = wsum[w]; wsum[w] = c; c += t2; }
    }
    __syncthreads();
    unsigned c = x - s + wsum[tid >> 5];
    const unsigned I0 = RANK0, I1 = RANK0 + 1;
    for (int i = 0; i < PER; i++) {
        unsigned cnt = hh[start + i];
        if (cnt) {
            if (I0 >= c && I0 < c + cnt) { g_b0[h] = start + i; g_base[h] = (int)c; }
            if (I1 >= c && I1 < c + cnt) { g_b1[h] = start + i; }
        }
        c += cnt;
    }
}

// ---------------- K5: compact candidates from target bins ----------------
__global__ __launch_bounds__(1024) void compact_kernel() {
    int h = blockIdx.y;
    int B0 = g_b0[h], B1 = g_b1[h];
    const size_t per_head = (size_t)SS * SS;
    const float4* base = (const float4*)(g_scores + (size_t)h * per_head);
    size_t n4 = per_head / 4;
    size_t idx = (size_t)blockIdx.x * blockDim.x + threadIdx.x;
    size_t stride = (size_t)gridDim.x * blockDim.x;
    for (size_t i = idx; i < n4; i += stride) {
        float4 v = base[i];
        float vals[4] = {v.x, v.y, v.z, v.w};
#pragma unroll
        for (int t = 0; t < 4; t++) {
            int b = score_bin(vals[t]);
            if (b == B0 || b == B1) {
                int p = atomicAdd(&g_cnt[h], 1);
                if (p < CCAP) g_cand[h * CCAP + p] = vals[t];
            }
        }
    }
}

// ---------------- K6: sort candidates (dynamic pow2 bitonic), exact quantile ----
__global__ __launch_bounds__(1024) void select_kernel() {
    extern __shared__ float sm[];
    int h = blockIdx.x;
    int n = min(g_cnt[h], CCAP);
    int m = 1024;
    while (m < n) m <<= 1;
    for (int i = threadIdx.x; i < m; i += blockDim.x)
        sm[i] = (i < n) ? g_cand[h * CCAP + i] : inf_f();
    __syncthreads();
    for (int k = 2; k <= m; k <<= 1) {
        for (int j = k >> 1; j > 0; j >>= 1) {
            for (int i = threadIdx.x; i < m; i += blockDim.x) {
                int ixj = i ^ j;
                if (ixj > i) {
                    bool up = ((i & k) == 0);
                    float a = sm[i], b = sm[ixj];
                    if ((a > b) == up) { sm[i] = b; sm[ixj] = a; }
                }
            }
            __syncthreads();
        }
    }
    if (threadIdx.x == 0) {
        float idxf = 0.95f * (float)(SS * SS - 1);
        float frac = idxf - floorf(idxf);   // 0.75 in fp32
        int r0 = RANK0 - g_base[h];
        if (r0 < 0) r0 = 0;
        if (r0 > n - 2) r0 = n - 2;
        float v0 = sm[r0], v1 = sm[r0 + 1];
        g_thr[h] = v0 + frac * (v1 - v0);
    }
}

// ---------------- K7: masked softmax + attn@V, chunked compaction ----------------
#define CH 512
__global__ __launch_bounds__(256) void attn_kernel() {
    __shared__ float          sv[8][CH];
    __shared__ unsigned short si[8][CH];
    int h = blockIdx.y;
    int warp = threadIdx.x >> 5;
    int lane = threadIdx.x & 31;
    int row = blockIdx.x * 8 + warp;
    float t = g_thr[h];
    const float* srow = g_scores + ((size_t)h * SS + row) * SS;
    const float* vh = g_v + h * HDIM;
    const float NEG = -inf_f();
    float m = NEG, l = 0.f, acc0 = 0.f, acc1 = 0.f;
    for (int c0 = 0; c0 < SS; c0 += CH) {
        int cnt = 0;
        float lmax = NEG;
#pragma unroll
        for (int cc = 0; cc < CH; cc += 32) {
            float s = srow[c0 + cc + lane];
            bool kept = (s >= t);
            unsigned bal = __ballot_sync(0xffffffffu, kept);
            if (kept) {
                int pos = cnt + __popc(bal & ((1u << lane) - 1u));
                sv[warp][pos] = s;
                si[warp][pos] = (unsigned short)(c0 + cc + lane);
                lmax = fmaxf(lmax, s);
            }
            cnt += __popc(bal);
        }
        if (cnt == 0) continue;
#pragma unroll
        for (int o = 16; o; o >>= 1) lmax = fmaxf(lmax, __shfl_xor_sync(0xffffffffu, lmax, o));
        if (lmax > m) {
            float corr = (m == NEG) ? 0.f : __expf(m - lmax);
            l *= corr; acc0 *= corr; acc1 *= corr;
            m = lmax;
        }
        __syncwarp();
        for (int i = lane; i < cnt; i += 32)
            sv[warp][i] = __expf(sv[warp][i] - m);
        __syncwarp();
        int i = 0;
        for (; i + 4 <= cnt; i += 4) {
            float p0 = sv[warp][i + 0], p1 = sv[warp][i + 1];
            float p2 = sv[warp][i + 2], p3 = sv[warp][i + 3];
            const float* v0 = vh + (size_t)si[warp][i + 0] * DD;
            const float* v1 = vh + (size_t)si[warp][i + 1] * DD;
            const float* v2 = vh + (size_t)si[warp][i + 2] * DD;
            const float* v3 = vh + (size_t)si[warp][i + 3] * DD;
            acc0 += p0 * v0[lane]      + p1 * v1[lane]      + p2 * v2[lane]      + p3 * v3[lane];
            acc1 += p0 * v0[lane + 32] + p1 * v1[lane + 32] + p2 * v2[lane + 32] + p3 * v3[lane + 32];
            l += p0 + p1 + p2 + p3;
        }
        for (; i < cnt; ++i) {
            float p = sv[warp][i];
            const float* vr = vh + (size_t)si[warp][i] * DD;
            acc0 += p * vr[lane];
            acc1 += p * vr[lane + 32];
            l += p;
        }
        __syncwarp();
    }
    float inv = (l > 0.f) ? 1.f / l : 0.f;
    g_o[(size_t)row * DD + h * HDIM + lane]      = acc0 * inv;
    g_o[(size_t)row * DD + h * HDIM + lane + 32] = acc1 * inv;
}

// ---------------- launch ----------------
extern "C" void kernel_launch(void* const* d_in, const int* in_sizes, int n_in,
                              void* d_out, int out_size) {
    (void)in_sizes; (void)n_in; (void)out_size;
    const float* x  = (const float*)d_in[0];
    const float* Wq = (const float*)d_in[1];
    const float* bq = (const float*)d_in[2];
    const float* Wk = (const float*)d_in[3];
    const float* bk = (const float*)d_in[4];
    const float* Wv = (const float*)d_in[5];
    const float* bv = (const float*)d_in[6];
    const float* Wo = (const float*)d_in[7];
    const float* bo = (const float*)d_in[8];
    float* out = (float*)d_out;

    const int TF32_SMEM = 8192 * sizeof(float2);   // 64 KB

    cudaFuncSetAttribute(scores_kernel,  cudaFuncAttributeMaxDynamicSharedMemorySize, NBINS * 4);
    cudaFuncSetAttribute(v_kernel,       cudaFuncAttributeMaxDynamicSharedMemorySize, TF32_SMEM);
    cudaFuncSetAttribute(outproj_kernel, cudaFuncAttributeMaxDynamicSharedMemorySize, TF32_SMEM);
    cudaFuncSetAttribute(select_kernel,  cudaFuncAttributeMaxDynamicSharedMemorySize, CCAP * 4);

    float *pq, *pk, *pv, *po;
    cudaGetSymbolAddress((void**)&pq, g_q);
    cudaGetSymbolAddress((void**)&pk, g_k);
    cudaGetSymbolAddress((void**)&pv, g_v);
    cudaGetSymbolAddress((void**)&po, g_o);

    zero_kernel<<<(NH * NBINS + 255) / 256, 256>>>();
    qk_kernel<<<dim3(DD / BN, SS / BM, 2), 256>>>(x, Wq, bq, Wk, bk, pq, pk);
    v_kernel<<<dim3(DD / 128, SS / 128), 256, TF32_SMEM>>>(x, Wv, bv, pv);
    scores_kernel<<<dim3(SS / BN, SS / BM, NH), 256, NBINS * 4>>>();
    findbin_kernel<<<NH, 256>>>();
    compact_kernel<<<dim3(32, NH), 1024>>>();
    select_kernel<<<NH, 1024, CCAP * 4>>>();
    attn_kernel<<<dim3(SS / 8, NH), 256>>>();
    outproj_kernel<<<dim3(DD / 128, SS / 128), 256, TF32_SMEM>>>(po, Wo, bo, out);
}

// round 11
// speedup vs baseline: 1.1006x; 1.1006x over previous
#include <cuda_runtime.h>
#include <cstdint>

#define SS   2048
#define DD   1024
#define NH   16
#define HDIM 64
#define NBINS 8192
#define CCAP  32768
#define RANK0 3984587

#define BM 128
#define BN 128
#define BK 16
#define TM 8
#define TN 8

// ---------------- scratch ----------------
__device__ float g_q[SS * DD];
__device__ float g_k[SS * DD];
__device__ float g_v[SS * DD];
__device__ float g_o[SS * DD];
__device__ float g_scores[(size_t)NH * SS * SS];   // 256 MB
__device__ unsigned g_hist[NH * NBINS];
__device__ float g_cand[NH * CCAP];
__device__ int g_cnt[NH];
__device__ int g_b0[NH], g_b1[NH], g_base[NH];
__device__ float g_thr[NH];

__device__ __forceinline__ float inf_f() { return __int_as_float(0x7f800000); }

__device__ __forceinline__ int score_bin(float v) {
    int b = __float2int_rd((v + 16.0f) * 256.0f);   // 8192 bins over [-16,16)
    return min(max(b, 0), NBINS - 1);
}

// ---------------- K0: zero per-launch state ----------------
__global__ void zero_kernel() {
    int i = blockIdx.x * blockDim.x + threadIdx.x;
    if (i < NH * NBINS) g_hist[i] = 0;
    if (i < NH) g_cnt[i] = 0;
}

// ---------------- double-buffered fp32 GEMM mainloop (K=1024 kernels) --------
template<int KTOT, bool BT>
__device__ __forceinline__ void gemm_mainloop(
    const float* __restrict__ A, int lda,
    const float* __restrict__ Bm, int ldb,
    int bm, int bn, float acc[TM][TN])
{
    __shared__ float As[2][BK][BM];
    __shared__ float Bs[2][BK][BN];
    const int tid = threadIdx.x;
    const int tr = (tid >> 4) * TM;
    const int tc = (tid & 15) * TN;

    const int ar0 = tid >> 2;           // 0..63
    const int ar1 = ar0 + 64;           // 64..127
    const int ac  = (tid & 3) * 4;      // 0,4,8,12
    const int br0 = tid >> 5;           // 0..7
    const int br1 = br0 + 8;
    const int bc  = (tid & 31) * 4;

    float4 pa0, pa1, pb0, pb1;

    auto loadT = [&](int k0) {
        pa0 = *(const float4*)&A[(size_t)(bm + ar0) * lda + k0 + ac];
        pa1 = *(const float4*)&A[(size_t)(bm + ar1) * lda + k0 + ac];
        if (BT) {
            pb0 = *(const float4*)&Bm[(size_t)(bn + ar0) * ldb + k0 + ac];
            pb1 = *(const float4*)&Bm[(size_t)(bn + ar1) * ldb + k0 + ac];
        } else {
            pb0 = *(const float4*)&Bm[(size_t)(k0 + br0) * ldb + bn + bc];
            pb1 = *(const float4*)&Bm[(size_t)(k0 + br1) * ldb + bn + bc];
        }
    };
    auto storeT = [&](int buf) {
        As[buf][ac + 0][ar0] = pa0.x; As[buf][ac + 1][ar0] = pa0.y;
        As[buf][ac + 2][ar0] = pa0.z; As[buf][ac + 3][ar0] = pa0.w;
        As[buf][ac + 0][ar1] = pa1.x; As[buf][ac + 1][ar1] = pa1.y;
        As[buf][ac + 2][ar1] = pa1.z; As[buf][ac + 3][ar1] = pa1.w;
        if (BT) {
            Bs[buf][ac + 0][ar0] = pb0.x; Bs[buf][ac + 1][ar0] = pb0.y;
            Bs[buf][ac + 2][ar0] = pb0.z; Bs[buf][ac + 3][ar0] = pb0.w;
            Bs[buf][ac + 0][ar1] = pb1.x; Bs[buf][ac + 1][ar1] = pb1.y;
            Bs[buf][ac + 2][ar1] = pb1.z; Bs[buf][ac + 3][ar1] = pb1.w;
        } else {
            *(float4*)&Bs[buf][br0][bc] = pb0;
            *(float4*)&Bs[buf][br1][bc] = pb1;
        }
    };

    loadT(0);
    storeT(0);
    __syncthreads();
    const int NIT = KTOT / BK;
    for (int it = 0; it < NIT; ++it) {
        int buf = it & 1;
        if (it + 1 < NIT) loadT((it + 1) * BK);
#pragma unroll
        for (int kk = 0; kk < BK; ++kk) {
            float4 a0 = *(const float4*)&As[buf][kk][tr];
            float4 a1 = *(const float4*)&As[buf][kk][tr + 4];
            float4 b0 = *(const float4*)&Bs[buf][kk][tc];
            float4 b1 = *(const float4*)&Bs[buf][kk][tc + 4];
            float af[TM] = {a0.x, a0.y, a0.z, a0.w, a1.x, a1.y, a1.z, a1.w};
            float bf[TN] = {b0.x, b0.y, b0.z, b0.w, b1.x, b1.y, b1.z, b1.w};
#pragma unroll
            for (int i = 0; i < TM; i++)
#pragma unroll
                for (int j = 0; j < TN; j++)
                    acc[i][j] += af[i] * bf[j];
        }
        if (it + 1 < NIT) storeT(buf ^ 1);
        __syncthreads();
    }
}

// ---------------- K1: fused QKV projection ----------------
__global__ __launch_bounds__(256, 2) void qkv_kernel(
    const float* __restrict__ x,
    const float* __restrict__ Wq, const float* __restrict__ bq,
    const float* __restrict__ Wk, const float* __restrict__ bk,
    const float* __restrict__ Wv, const float* __restrict__ bv,
    float* __restrict__ q, float* __restrict__ k, float* __restrict__ v)
{
    const float* W; const float* bias; float* C;
    if (blockIdx.z == 0)      { W = Wq; bias = bq; C = q; }
    else if (blockIdx.z == 1) { W = Wk; bias = bk; C = k; }
    else                      { W = Wv; bias = bv; C = v; }

    int bm = blockIdx.y * BM, bn = blockIdx.x * BN;
    int tid = threadIdx.x;
    int tr = (tid >> 4) * TM, tc = (tid & 15) * TN;
    float acc[TM][TN] = {};
    gemm_mainloop<DD, false>(x, DD, W, DD, bm, bn, acc);
#pragma unroll
    for (int i = 0; i < TM; i++) {
        int row = bm + tr + i;
#pragma unroll
        for (int j = 0; j < TN; j += 4) {
            float4 r;
            r.x = acc[i][j + 0] + bias[bn + tc + j + 0];
            r.y = acc[i][j + 1] + bias[bn + tc + j + 1];
            r.z = acc[i][j + 2] + bias[bn + tc + j + 2];
            r.w = acc[i][j + 3] + bias[bn + tc + j + 3];
            *(float4*)&C[(size_t)row * DD + bn + tc + j] = r;
        }
    }
}

// ---------------- K8: output projection ----------------
__global__ __launch_bounds__(256, 2) void outproj_kernel(
    const float* __restrict__ A, const float* __restrict__ W,
    const float* __restrict__ bias, float* __restrict__ C)
{
    int bm = blockIdx.y * BM, bn = blockIdx.x * BN;
    int tid = threadIdx.x;
    int tr = (tid >> 4) * TM, tc = (tid & 15) * TN;
    float acc[TM][TN] = {};
    gemm_mainloop<DD, false>(A, DD, W, DD, bm, bn, acc);
#pragma unroll
    for (int i = 0; i < TM; i++) {
        int row = bm + tr + i;
#pragma unroll
        for (int j = 0; j < TN; j += 4) {
            float4 r;
            r.x = acc[i][j + 0] + bias[bn + tc + j + 0];
            r.y = acc[i][j + 1] + bias[bn + tc + j + 1];
            r.z = acc[i][j + 2] + bias[bn + tc + j + 2];
            r.w = acc[i][j + 3] + bias[bn + tc + j + 3];
            *(float4*)&C[(size_t)row * DD + bn + tc + j] = r;
        }
    }
}

// ---------------- K2: scores (full-K-resident smem) + fused histogram --------
// K=64 fits entirely in smem: load once, one barrier, 64 straight FMA steps.
// Per-accumulator k-order identical to R6's BK=16 pipeline -> bit-identical.
__global__ __launch_bounds__(256, 2) void scores_kernel() {
    extern __shared__ float smem[];
    float* As = smem;                       // [64][128] k-major: As[k*128+m]
    float* Bs = smem + 64 * 128;            // [64][128]
    unsigned* shh = (unsigned*)(smem + 2 * 64 * 128);   // NBINS

    int h = blockIdx.z;
    int bm = blockIdx.y * BM, bn = blockIdx.x * BN;
    int tid = threadIdx.x;
    int tr = (tid >> 4) * TM, tc = (tid & 15) * TN;

    for (int i = tid; i < NBINS; i += 256) shh[i] = 0;

    // cooperative load: 128 rows x 64 cols (fp32) each for A (q) and B (k)
    const float* qh = g_q + h * HDIM;
    const float* kh = g_k + h * HDIM;
    {
        int r = tid >> 1;                   // 0..127
        int f0 = (tid & 1) * 8;             // first float4 index (of 16 per row)
#pragma unroll
        for (int i = 0; i < 8; i++) {
            int col = (f0 + i) * 4;
            float4 a = *(const float4*)&qh[(size_t)(bm + r) * DD + col];
            As[(col + 0) * 128 + r] = a.x;
            As[(col + 1) * 128 + r] = a.y;
            As[(col + 2) * 128 + r] = a.z;
            As[(col + 3) * 128 + r] = a.w;
            float4 b = *(const float4*)&kh[(size_t)(bn + r) * DD + col];
            Bs[(col + 0) * 128 + r] = b.x;
            Bs[(col + 1) * 128 + r] = b.y;
            Bs[(col + 2) * 128 + r] = b.z;
            Bs[(col + 3) * 128 + r] = b.w;
        }
    }
    __syncthreads();

    float acc[TM][TN] = {};
#pragma unroll
    for (int kk = 0; kk < HDIM; ++kk) {
        float4 a0 = *(const float4*)&As[kk * 128 + tr];
        float4 a1 = *(const float4*)&As[kk * 128 + tr + 4];
        float4 b0 = *(const float4*)&Bs[kk * 128 + tc];
        float4 b1 = *(const float4*)&Bs[kk * 128 + tc + 4];
        float af[TM] = {a0.x, a0.y, a0.z, a0.w, a1.x, a1.y, a1.z, a1.w};
        float bf[TN] = {b0.x, b0.y, b0.z, b0.w, b1.x, b1.y, b1.z, b1.w};
#pragma unroll
        for (int i = 0; i < TM; i++)
#pragma unroll
            for (int j = 0; j < TN; j++)
                acc[i][j] += af[i] * bf[j];
    }
    __syncthreads();   // hist zeroing complete (and tile reads done)

    float* out = g_scores + (size_t)h * SS * SS;
#pragma unroll
    for (int i = 0; i < TM; i++) {
        size_t row = bm + tr + i;
#pragma unroll
        for (int j = 0; j < TN; j += 4) {
            float4 r;
            r.x = acc[i][j + 0] * 0.125f;
            r.y = acc[i][j + 1] * 0.125f;
            r.z = acc[i][j + 2] * 0.125f;
            r.w = acc[i][j + 3] * 0.125f;
            *(float4*)&out[row * SS + bn + tc + j] = r;
            atomicAdd(&shh[score_bin(r.x)], 1u);
            atomicAdd(&shh[score_bin(r.y)], 1u);
            atomicAdd(&shh[score_bin(r.z)], 1u);
            atomicAdd(&shh[score_bin(r.w)], 1u);
        }
    }
    __syncthreads();
    unsigned* gh = g_hist + h * NBINS;
    for (int i = tid; i < NBINS; i += 256) {
        unsigned c = shh[i];
        if (c) atomicAdd(&gh[i], c);
    }
}

// ---------------- K4: find bins containing ranks RANK0, RANK0+1 ----------------
__global__ __launch_bounds__(256) void findbin_kernel() {
    int h = blockIdx.x;
    const unsigned* hh = g_hist + h * NBINS;
    int tid = threadIdx.x;
    const int PER = NBINS / 256;   // 32
    int start = tid * PER;
    unsigned s = 0;
#pragma unroll
    for (int i = 0; i < PER; i++) s += hh[start + i];
    unsigned x = s;
#pragma unroll
    for (int o = 1; o < 32; o <<= 1) {
        unsigned y = __shfl_up_sync(0xffffffffu, x, o);
        if ((tid & 31) >= o) x += y;
    }
    __shared__ unsigned wsum[8];
    if ((tid & 31) == 31) wsum[tid >> 5] = x;
    __syncthreads();
    if (tid == 0) {
        unsigned c = 0;
        for (int w = 0; w < 8; w++) { unsigned t2 = wsum[w]; wsum[w] = c; c += t2; }
    }
    __syncthreads();
    unsigned c = x - s + wsum[tid >> 5];
    const unsigned I0 = RANK0, I1 = RANK0 + 1;
    for (int i = 0; i < PER; i++) {
        unsigned cnt = hh[start + i];
        if (cnt) {
            if (I0 >= c && I0 < c + cnt) { g_b0[h] = start + i; g_base[h] = (int)c; }
            if (I1 >= c && I1 < c + cnt) { g_b1[h] = start + i; }
        }
        c += cnt;
    }
}

// ---------------- K5: compact candidates from target bins ----------------
__global__ __launch_bounds__(1024) void compact_kernel() {
    int h = blockIdx.y;
    int B0 = g_b0[h], B1 = g_b1[h];
    const size_t per_head = (size_t)SS * SS;
    const float4* base = (const float4*)(g_scores + (size_t)h * per_head);
    size_t n4 = per_head / 4;
    size_t idx = (size_t)blockIdx.x * blockDim.x + threadIdx.x;
    size_t stride = (size_t)gridDim.x * blockDim.x;
    for (size_t i = idx; i < n4; i += stride) {
        float4 v = base[i];
        float vals[4] = {v.x, v.y, v.z, v.w};
#pragma unroll
        for (int t = 0; t < 4; t++) {
            int b = score_bin(vals[t]);
            if (b == B0 || b == B1) {
                int p = atomicAdd(&g_cnt[h], 1);
                if (p < CCAP) g_cand[h * CCAP + p] = vals[t];
            }
        }
    }
}

// ---------------- K6: sort candidates (dynamic pow2 bitonic), exact quantile ----
__global__ __launch_bounds__(1024) void select_kernel() {
    extern __shared__ float sm[];
    int h = blockIdx.x;
    int n = min(g_cnt[h], CCAP);
    int m = 1024;
    while (m < n) m <<= 1;
    for (int i = threadIdx.x; i < m; i += blockDim.x)
        sm[i] = (i < n) ? g_cand[h * CCAP + i] : inf_f();
    __syncthreads();
    for (int k = 2; k <= m; k <<= 1) {
        for (int j = k >> 1; j > 0; j >>= 1) {
            for (int i = threadIdx.x; i < m; i += blockDim.x) {
                int ixj = i ^ j;
                if (ixj > i) {
                    bool up = ((i & k) == 0);
                    float a = sm[i], b = sm[ixj];
                    if ((a > b) == up) { sm[i] = b; sm[ixj] = a; }
                }
            }
            __syncthreads();
        }
    }
    if (threadIdx.x == 0) {
        float idxf = 0.95f * (float)(SS * SS - 1);
        float frac = idxf - floorf(idxf);   // 0.75 in fp32
        int r0 = RANK0 - g_base[h];
        if (r0 < 0) r0 = 0;
        if (r0 > n - 2) r0 = n - 2;
        float v0 = sm[r0], v1 = sm[r0 + 1];
        g_thr[h] = v0 + frac * (v1 - v0);
    }
}

// ---------------- K7: masked softmax + attn@V, chunked compaction ----------------
#define CH 512
__global__ __launch_bounds__(256) void attn_kernel() {
    __shared__ float          sv[8][CH];
    __shared__ unsigned short si[8][CH];
    int h = blockIdx.y;
    int warp = threadIdx.x >> 5;
    int lane = threadIdx.x & 31;
    int row = blockIdx.x * 8 + warp;
    float t = g_thr[h];
    const float* srow = g_scores + ((size_t)h * SS + row) * SS;
    const float* vh = g_v + h * HDIM;
    const float NEG = -inf_f();
    float m = NEG, l = 0.f, acc0 = 0.f, acc1 = 0.f;
    for (int c0 = 0; c0 < SS; c0 += CH) {
        int cnt = 0;
        float lmax = NEG;
#pragma unroll
        for (int cc = 0; cc < CH; cc += 32) {
            float s = srow[c0 + cc + lane];
            bool kept = (s >= t);
            unsigned bal = __ballot_sync(0xffffffffu, kept);
            if (kept) {
                int pos = cnt + __popc(bal & ((1u << lane) - 1u));
                sv[warp][pos] = s;
                si[warp][pos] = (unsigned short)(c0 + cc + lane);
                lmax = fmaxf(lmax, s);
            }
            cnt += __popc(bal);
        }
        if (cnt == 0) continue;
#pragma unroll
        for (int o = 16; o; o >>= 1) lmax = fmaxf(lmax, __shfl_xor_sync(0xffffffffu, lmax, o));
        if (lmax > m) {
            float corr = (m == NEG) ? 0.f : __expf(m - lmax);
            l *= corr; acc0 *= corr; acc1 *= corr;
            m = lmax;
        }
        __syncwarp();
        for (int i = lane; i < cnt; i += 32)
            sv[warp][i] = __expf(sv[warp][i] - m);
        __syncwarp();
        int i = 0;
        for (; i + 4 <= cnt; i += 4) {
            float p0 = sv[warp][i + 0], p1 = sv[warp][i + 1];
            float p2 = sv[warp][i + 2], p3 = sv[warp][i + 3];
            const float* v0 = vh + (size_t)si[warp][i + 0] * DD;
            const float* v1 = vh + (size_t)si[warp][i + 1] * DD;
            const float* v2 = vh + (size_t)si[warp][i + 2] * DD;
            const float* v3 = vh + (size_t)si[warp][i + 3] * DD;
            acc0 += p0 * v0[lane]      + p1 * v1[lane]      + p2 * v2[lane]      + p3 * v3[lane];
            acc1 += p0 * v0[lane + 32] + p1 * v1[lane + 32] + p2 * v2[lane + 32] + p3 * v3[lane + 32];
            l += p0 + p1 + p2 + p3;
        }
        for (; i < cnt; ++i) {
            float p = sv[warp][i];
            const float* vr = vh + (size_t)si[warp][i] * DD;
            acc0 += p * vr[lane];
            acc1 += p * vr[lane + 32];
            l += p;
        }
        __syncwarp();
    }
    float inv = (l > 0.f) ? 1.f / l : 0.f;
    g_o[(size_t)row * DD + h * HDIM + lane]      = acc0 * inv;
    g_o[(size_t)row * DD + h * HDIM + lane + 32] = acc1 * inv;
}

// ---------------- launch ----------------
extern "C" void kernel_launch(void* const* d_in, const int* in_sizes, int n_in,
                              void* d_out, int out_size) {
    (void)in_sizes; (void)n_in; (void)out_size;
    const float* x  = (const float*)d_in[0];
    const float* Wq = (const float*)d_in[1];
    const float* bq = (const float*)d_in[2];
    const float* Wk = (const float*)d_in[3];
    const float* bk = (const float*)d_in[4];
    const float* Wv = (const float*)d_in[5];
    const float* bv = (const float*)d_in[6];
    const float* Wo = (const float*)d_in[7];
    const float* bo = (const float*)d_in[8];
    float* out = (float*)d_out;

    const int SCORES_SMEM = 2 * 64 * 128 * 4 + NBINS * 4;   // 64KB tiles + 32KB hist

    cudaFuncSetAttribute(scores_kernel, cudaFuncAttributeMaxDynamicSharedMemorySize, SCORES_SMEM);
    cudaFuncSetAttribute(select_kernel, cudaFuncAttributeMaxDynamicSharedMemorySize, CCAP * 4);

    float *pq, *pk, *pv, *po;
    cudaGetSymbolAddress((void**)&pq, g_q);
    cudaGetSymbolAddress((void**)&pk, g_k);
    cudaGetSymbolAddress((void**)&pv, g_v);
    cudaGetSymbolAddress((void**)&po, g_o);

    zero_kernel<<<(NH * NBINS + 255) / 256, 256>>>();
    qkv_kernel<<<dim3(DD / BN, SS / BM, 3), 256>>>(x, Wq, bq, Wk, bk, Wv, bv, pq, pk, pv);
    scores_kernel<<<dim3(SS / BN, SS / BM, NH), 256, SCORES_SMEM>>>();
    findbin_kernel<<<NH, 256>>>();
    compact_kernel<<<dim3(32, NH), 1024>>>();
    select_kernel<<<NH, 1024, CCAP * 4>>>();
    attn_kernel<<<dim3(SS / 8, NH), 256>>>();
    outproj_kernel<<<dim3(DD / BN, SS / BM), 256>>>(po, Wo, bo, out);
}

// round 12
// speedup vs baseline: 1.1684x; 1.0616x over previous
#include <cuda_runtime.h>
#include <cstdint>

#define SS   2048
#define DD   1024
#define NH   16
#define HDIM 64
#define NBINS 8192
#define CCAP  32768
#define RANK0 3984587

#define BM 128
#define BN 128
#define BK 16
#define TM 8
#define TN 8

// ---------------- scratch ----------------
__device__ float g_q[SS * DD];
__device__ float g_k[SS * DD];
__device__ float g_v[SS * DD];
__device__ float g_o[SS * DD];
__device__ float g_scores[(size_t)NH * SS * SS];   // 256 MB
__device__ unsigned g_hist[NH * NBINS];
__device__ float g_cand[NH * CCAP];
__device__ int g_cnt[NH];
__device__ float g_thr[NH];

__device__ __forceinline__ float inf_f() { return __int_as_float(0x7f800000); }

// 8192 bins over [-4,4): width 1/1024. Scores ~N(0,0.41): |s|>4 is ~9.7 sigma,
// clamp bins stay empty; threshold bin (~0.276) is interior. Exact order stats
// are preserved (bins only partition; selection interpolates true values).
__device__ __forceinline__ int score_bin(float v) {
    int b = __float2int_rd((v + 4.0f) * 1024.0f);
    return min(max(b, 0), NBINS - 1);
}

// ---------------- K0: zero per-launch state ----------------
__global__ void zero_kernel() {
    int i = blockIdx.x * blockDim.x + threadIdx.x;
    if (i < NH * NBINS) g_hist[i] = 0;
    if (i < NH) g_cnt[i] = 0;
}

// ---------------- double-buffered fp32 GEMM mainloop ----------------
template<int KTOT, bool BT>
__device__ __forceinline__ void gemm_mainloop(
    const float* __restrict__ A, int lda,
    const float* __restrict__ Bm, int ldb,
    int bm, int bn, float acc[TM][TN])
{
    __shared__ float As[2][BK][BM];
    __shared__ float Bs[2][BK][BN];
    const int tid = threadIdx.x;
    const int tr = (tid >> 4) * TM;
    const int tc = (tid & 15) * TN;

    const int ar0 = tid >> 2;           // 0..63
    const int ar1 = ar0 + 64;           // 64..127
    const int ac  = (tid & 3) * 4;      // 0,4,8,12
    const int br0 = tid >> 5;           // 0..7
    const int br1 = br0 + 8;
    const int bc  = (tid & 31) * 4;

    float4 pa0, pa1, pb0, pb1;

    auto loadT = [&](int k0) {
        pa0 = *(const float4*)&A[(size_t)(bm + ar0) * lda + k0 + ac];
        pa1 = *(const float4*)&A[(size_t)(bm + ar1) * lda + k0 + ac];
        if (BT) {
            pb0 = *(const float4*)&Bm[(size_t)(bn + ar0) * ldb + k0 + ac];
            pb1 = *(const float4*)&Bm[(size_t)(bn + ar1) * ldb + k0 + ac];
        } else {
            pb0 = *(const float4*)&Bm[(size_t)(k0 + br0) * ldb + bn + bc];
            pb1 = *(const float4*)&Bm[(size_t)(k0 + br1) * ldb + bn + bc];
        }
    };
    auto storeT = [&](int buf) {
        As[buf][ac + 0][ar0] = pa0.x; As[buf][ac + 1][ar0] = pa0.y;
        As[buf][ac + 2][ar0] = pa0.z; As[buf][ac + 3][ar0] = pa0.w;
        As[buf][ac + 0][ar1] = pa1.x; As[buf][ac + 1][ar1] = pa1.y;
        As[buf][ac + 2][ar1] = pa1.z; As[buf][ac + 3][ar1] = pa1.w;
        if (BT) {
            Bs[buf][ac + 0][ar0] = pb0.x; Bs[buf][ac + 1][ar0] = pb0.y;
            Bs[buf][ac + 2][ar0] = pb0.z; Bs[buf][ac + 3][ar0] = pb0.w;
            Bs[buf][ac + 0][ar1] = pb1.x; Bs[buf][ac + 1][ar1] = pb1.y;
            Bs[buf][ac + 2][ar1] = pb1.z; Bs[buf][ac + 3][ar1] = pb1.w;
        } else {
            *(float4*)&Bs[buf][br0][bc] = pb0;
            *(float4*)&Bs[buf][br1][bc] = pb1;
        }
    };

    loadT(0);
    storeT(0);
    __syncthreads();
    const int NIT = KTOT / BK;
    for (int it = 0; it < NIT; ++it) {
        int buf = it & 1;
        if (it + 1 < NIT) loadT((it + 1) * BK);
#pragma unroll
        for (int kk = 0; kk < BK; ++kk) {
            float4 a0 = *(const float4*)&As[buf][kk][tr];
            float4 a1 = *(const float4*)&As[buf][kk][tr + 4];
            float4 b0 = *(const float4*)&Bs[buf][kk][tc];
            float4 b1 = *(const float4*)&Bs[buf][kk][tc + 4];
            float af[TM] = {a0.x, a0.y, a0.z, a0.w, a1.x, a1.y, a1.z, a1.w};
            float bf[TN] = {b0.x, b0.y, b0.z, b0.w, b1.x, b1.y, b1.z, b1.w};
#pragma unroll
            for (int i = 0; i < TM; i++)
#pragma unroll
                for (int j = 0; j < TN; j++)
                    acc[i][j] += af[i] * bf[j];
        }
        if (it + 1 < NIT) storeT(buf ^ 1);
        __syncthreads();
    }
}

// ---------------- K1: fused QKV projection ----------------
__global__ __launch_bounds__(256, 2) void qkv_kernel(
    const float* __restrict__ x,
    const float* __restrict__ Wq, const float* __restrict__ bq,
    const float* __restrict__ Wk, const float* __restrict__ bk,
    const float* __restrict__ Wv, const float* __restrict__ bv,
    float* __restrict__ q, float* __restrict__ k, float* __restrict__ v)
{
    const float* W; const float* bias; float* C;
    if (blockIdx.z == 0)      { W = Wq; bias = bq; C = q; }
    else if (blockIdx.z == 1) { W = Wk; bias = bk; C = k; }
    else                      { W = Wv; bias = bv; C = v; }

    int bm = blockIdx.y * BM, bn = blockIdx.x * BN;
    int tid = threadIdx.x;
    int tr = (tid >> 4) * TM, tc = (tid & 15) * TN;
    float acc[TM][TN] = {};
    gemm_mainloop<DD, false>(x, DD, W, DD, bm, bn, acc);
#pragma unroll
    for (int i = 0; i < TM; i++) {
        int row = bm + tr + i;
#pragma unroll
        for (int j = 0; j < TN; j += 4) {
            float4 r;
            r.x = acc[i][j + 0] + bias[bn + tc + j + 0];
            r.y = acc[i][j + 1] + bias[bn + tc + j + 1];
            r.z = acc[i][j + 2] + bias[bn + tc + j + 2];
            r.w = acc[i][j + 3] + bias[bn + tc + j + 3];
            *(float4*)&C[(size_t)row * DD + bn + tc + j] = r;
        }
    }
}

// ---------------- K8: output projection ----------------
__global__ __launch_bounds__(256, 2) void outproj_kernel(
    const float* __restrict__ A, const float* __restrict__ W,
    const float* __restrict__ bias, float* __restrict__ C)
{
    int bm = blockIdx.y * BM, bn = blockIdx.x * BN;
    int tid = threadIdx.x;
    int tr = (tid >> 4) * TM, tc = (tid & 15) * TN;
    float acc[TM][TN] = {};
    gemm_mainloop<DD, false>(A, DD, W, DD, bm, bn, acc);
#pragma unroll
    for (int i = 0; i < TM; i++) {
        int row = bm + tr + i;
#pragma unroll
        for (int j = 0; j < TN; j += 4) {
            float4 r;
            r.x = acc[i][j + 0] + bias[bn + tc + j + 0];
            r.y = acc[i][j + 1] + bias[bn + tc + j + 1];
            r.z = acc[i][j + 2] + bias[bn + tc + j + 2];
            r.w = acc[i][j + 3] + bias[bn + tc + j + 3];
            *(float4*)&C[(size_t)row * DD + bn + tc + j] = r;
        }
    }
}

// ---------------- K2: scores = q_h @ k_h^T * 0.125, fused histogram ----------
// (R6 double-buffered mainloop: gmem loads overlap FMA work.)
__global__ __launch_bounds__(256, 2) void scores_kernel() {
    extern __shared__ unsigned shh[];   // NBINS -> 32 KB dynamic
    int h = blockIdx.z;
    int bm = blockIdx.y * BM, bn = blockIdx.x * BN;
    int tid = threadIdx.x;
    int tr = (tid >> 4) * TM, tc = (tid & 15) * TN;

    for (int i = tid; i < NBINS; i += 256) shh[i] = 0;

    float acc[TM][TN] = {};
    gemm_mainloop<HDIM, true>(g_q + h * HDIM, DD, g_k + h * HDIM, DD, bm, bn, acc);
    // mainloop ends with __syncthreads(): shh zeroing complete.

    float* out = g_scores + (size_t)h * SS * SS;
#pragma unroll
    for (int i = 0; i < TM; i++) {
        size_t row = bm + tr + i;
#pragma unroll
        for (int j = 0; j < TN; j += 4) {
            float4 r;
            r.x = acc[i][j + 0] * 0.125f;
            r.y = acc[i][j + 1] * 0.125f;
            r.z = acc[i][j + 2] * 0.125f;
            r.w = acc[i][j + 3] * 0.125f;
            *(float4*)&out[row * SS + bn + tc + j] = r;
            atomicAdd(&shh[score_bin(r.x)], 1u);
            atomicAdd(&shh[score_bin(r.y)], 1u);
            atomicAdd(&shh[score_bin(r.z)], 1u);
            atomicAdd(&shh[score_bin(r.w)], 1u);
        }
    }
    __syncthreads();
    unsigned* gh = g_hist + h * NBINS;
    for (int i = tid; i < NBINS; i += 256) {
        unsigned c = shh[i];
        if (c) atomicAdd(&gh[i], c);
    }
}

// ---------------- inline rank-scan over g_hist (replaces findbin_kernel) -----
// Threads [0,256) cooperate; results broadcast via the provided shared slots.
// Finds bins holding global ranks RANK0 and RANK0+1 plus the prefix base of b0.
__device__ __forceinline__ void rank_scan_256(
    const unsigned* __restrict__ hh, int tid,
    unsigned* wsum /*[8] shared*/, int* sb0, int* sb1, int* sbase)
{
    const int PER = NBINS / 256;   // 32
    int start = tid * PER;
    unsigned s = 0;
#pragma unroll
    for (int i = 0; i < PER; i++) s += hh[start + i];
    unsigned x = s;
#pragma unroll
    for (int o = 1; o < 32; o <<= 1) {
        unsigned y = __shfl_up_sync(0xffffffffu, x, o);
        if ((tid & 31) >= o) x += y;
    }
    if ((tid & 31) == 31) wsum[tid >> 5] = x;
    __syncthreads();
    if (tid == 0) {
        unsigned c = 0;
        for (int w = 0; w < 8; w++) { unsigned t2 = wsum[w]; wsum[w] = c; c += t2; }
    }
    __syncthreads();
    unsigned c = x - s + wsum[tid >> 5];
    const unsigned I0 = RANK0, I1 = RANK0 + 1;
    for (int i = 0; i < PER; i++) {
        unsigned cnt = hh[start + i];
        if (cnt) {
            if (I0 >= c && I0 < c + cnt) { *sb0 = start + i; *sbase = (int)c; }
            if (I1 >= c && I1 < c + cnt) { *sb1 = start + i; }
        }
        c += cnt;
    }
}

// ---------------- K5: compact candidates (computes its own b0/b1) ------------
__global__ __launch_bounds__(1024) void compact_kernel() {
    __shared__ unsigned wsum[8];
    __shared__ int sb0, sb1, sbase;
    int h = blockIdx.y;
    int tid = threadIdx.x;
    if (tid < 256) rank_scan_256(g_hist + h * NBINS, tid, wsum, &sb0, &sb1, &sbase);
    else { __syncthreads(); __syncthreads(); }   // match the two barriers inside
    __syncthreads();
    int B0 = sb0, B1 = sb1;

    const size_t per_head = (size_t)SS * SS;
    const float4* base = (const float4*)(g_scores + (size_t)h * per_head);
    size_t n4 = per_head / 4;
    size_t idx = (size_t)blockIdx.x * blockDim.x + tid;
    size_t stride = (size_t)gridDim.x * blockDim.x;
    for (size_t i = idx; i < n4; i += stride) {
        float4 v = base[i];
        float vals[4] = {v.x, v.y, v.z, v.w};
#pragma unroll
        for (int t = 0; t < 4; t++) {
            int b = score_bin(vals[t]);
            if (b == B0 || b == B1) {
                int p = atomicAdd(&g_cnt[h], 1);
                if (p < CCAP) g_cand[h * CCAP + p] = vals[t];
            }
        }
    }
}

// ---------------- K6: sort candidates, exact quantile (computes own base) ----
__global__ __launch_bounds__(1024) void select_kernel() {
    extern __shared__ float sm[];
    __shared__ unsigned wsum[8];
    __shared__ int sb0, sb1, sbase;
    int h = blockIdx.x;
    int tid = threadIdx.x;
    if (tid < 256) rank_scan_256(g_hist + h * NBINS, tid, wsum, &sb0, &sb1, &sbase);
    else { __syncthreads(); __syncthreads(); }
    __syncthreads();

    int n = min(g_cnt[h], CCAP);
    int m = 1024;
    while (m < n) m <<= 1;
    for (int i = tid; i < m; i += blockDim.x)
        sm[i] = (i < n) ? g_cand[h * CCAP + i] : inf_f();
    __syncthreads();
    for (int k = 2; k <= m; k <<= 1) {
        for (int j = k >> 1; j > 0; j >>= 1) {
            for (int i = tid; i < m; i += blockDim.x) {
                int ixj = i ^ j;
                if (ixj > i) {
                    bool up = ((i & k) == 0);
                    float a = sm[i], b = sm[ixj];
                    if ((a > b) == up) { sm[i] = b; sm[ixj] = a; }
                }
            }
            __syncthreads();
        }
    }
    if (tid == 0) {
        float idxf = 0.95f * (float)(SS * SS - 1);
        float frac = idxf - floorf(idxf);   // 0.75 in fp32
        int r0 = RANK0 - sbase;
        if (r0 < 0) r0 = 0;
        if (r0 > n - 2) r0 = n - 2;
        float v0 = sm[r0], v1 = sm[r0 + 1];
        g_thr[h] = v0 + frac * (v1 - v0);
    }
}

// ---------------- K7: masked softmax + attn@V, chunked compaction ----------------
#define CH 512
__global__ __launch_bounds__(256) void attn_kernel() {
    __shared__ float          sv[8][CH];
    __shared__ unsigned short si[8][CH];
    int h = blockIdx.y;
    int warp = threadIdx.x >> 5;
    int lane = threadIdx.x & 31;
    int row = blockIdx.x * 8 + warp;
    float t = g_thr[h];
    const float* srow = g_scores + ((size_t)h * SS + row) * SS;
    const float* vh = g_v + h * HDIM;
    const float NEG = -inf_f();
    float m = NEG, l = 0.f, acc0 = 0.f, acc1 = 0.f;
    for (int c0 = 0; c0 < SS; c0 += CH) {
        int cnt = 0;
        float lmax = NEG;
#pragma unroll
        for (int cc = 0; cc < CH; cc += 32) {
            float s = srow[c0 + cc + lane];
            bool kept = (s >= t);
            unsigned bal = __ballot_sync(0xffffffffu, kept);
            if (kept) {
                int pos = cnt + __popc(bal & ((1u << lane) - 1u));
                sv[warp][pos] = s;
                si[warp][pos] = (unsigned short)(c0 + cc + lane);
                lmax = fmaxf(lmax, s);
            }
            cnt += __popc(bal);
        }
        if (cnt == 0) continue;
#pragma unroll
        for (int o = 16; o; o >>= 1) lmax = fmaxf(lmax, __shfl_xor_sync(0xffffffffu, lmax, o));
        if (lmax > m) {
            float corr = (m == NEG) ? 0.f : __expf(m - lmax);
            l *= corr; acc0 *= corr; acc1 *= corr;
            m = lmax;
        }
        __syncwarp();
        for (int i = lane; i < cnt; i += 32)
            sv[warp][i] = __expf(sv[warp][i] - m);
        __syncwarp();
        int i = 0;
        for (; i + 4 <= cnt; i += 4) {
            float p0 = sv[warp][i + 0], p1 = sv[warp][i + 1];
            float p2 = sv[warp][i + 2], p3 = sv[warp][i + 3];
            const float* v0 = vh + (size_t)si[warp][i + 0] * DD;
            const float* v1 = vh + (size_t)si[warp][i + 1] * DD;
            const float* v2 = vh + (size_t)si[warp][i + 2] * DD;
            const float* v3 = vh + (size_t)si[warp][i + 3] * DD;
            acc0 += p0 * v0[lane]      + p1 * v1[lane]      + p2 * v2[lane]      + p3 * v3[lane];
            acc1 += p0 * v0[lane + 32] + p1 * v1[lane + 32] + p2 * v2[lane + 32] + p3 * v3[lane + 32];
            l += p0 + p1 + p2 + p3;
        }
        for (; i < cnt; ++i) {
            float p = sv[warp][i];
            const float* vr = vh + (size_t)si[warp][i] * DD;
            acc0 += p * vr[lane];
            acc1 += p * vr[lane + 32];
            l += p;
        }
        __syncwarp();
    }
    float inv = (l > 0.f) ? 1.f / l : 0.f;
    g_o[(size_t)row * DD + h * HDIM + lane]      = acc0 * inv;
    g_o[(size_t)row * DD + h * HDIM + lane + 32] = acc1 * inv;
}

// ---------------- launch ----------------
extern "C" void kernel_launch(void* const* d_in, const int* in_sizes, int n_in,
                              void* d_out, int out_size) {
    (void)in_sizes; (void)n_in; (void)out_size;
    const float* x  = (const float*)d_in[0];
    const float* Wq = (const float*)d_in[1];
    const float* bq = (const float*)d_in[2];
    const float* Wk = (const float*)d_in[3];
    const float* bk = (const float*)d_in[4];
    const float* Wv = (const float*)d_in[5];
    const float* bv = (const float*)d_in[6];
    const float* Wo = (const float*)d_in[7];
    const float* bo = (const float*)d_in[8];
    float* out = (float*)d_out;

    cudaFuncSetAttribute(scores_kernel, cudaFuncAttributeMaxDynamicSharedMemorySize, NBINS * 4);
    cudaFuncSetAttribute(select_kernel, cudaFuncAttributeMaxDynamicSharedMemorySize, CCAP * 4);

    float *pq, *pk, *pv, *po;
    cudaGetSymbolAddress((void**)&pq, g_q);
    cudaGetSymbolAddress((void**)&pk, g_k);
    cudaGetSymbolAddress((void**)&pv, g_v);
    cudaGetSymbolAddress((void**)&po, g_o);

    zero_kernel<<<(NH * NBINS + 255) / 256, 256>>>();
    qkv_kernel<<<dim3(DD / BN, SS / BM, 3), 256>>>(x, Wq, bq, Wk, bk, Wv, bv, pq, pk, pv);
    scores_kernel<<<dim3(SS / BN, SS / BM, NH), 256, NBINS * 4>>>();
    compact_kernel<<<dim3(32, NH), 1024>>>();
    select_kernel<<<NH, 1024, CCAP * 4>>>();
    attn_kernel<<<dim3(SS / 8, NH), 256>>>();
    outproj_kernel<<<dim3(DD / BN, SS / BM), 256>>>(po, Wo, bo, out);
}

// round 13
// speedup vs baseline: 1.2081x; 1.0340x over previous
#include <cuda_runtime.h>
#include <cstdint>

#define SS   2048
#define DD   1024
#define NH   16
#define HDIM 64
#define NBINS 8192
#define CCAP  32768
#define RANK0 3984587

#define BM 128
#define BN 128
#define BK 16
#define TM 8
#define TN 8

// ---------------- scratch ----------------
__device__ float g_q[SS * DD];
__device__ float g_k[SS * DD];
__device__ float g_v[SS * DD];
__device__ float g_o[SS * DD];
__device__ float g_scores[(size_t)NH * SS * SS];   // 256 MB
__device__ unsigned g_hist[NH * NBINS];
__device__ float g_cand[NH * CCAP];
__device__ int g_cnt[NH];
__device__ float g_thr[NH];

__device__ __forceinline__ float inf_f() { return __int_as_float(0x7f800000); }

// 8192 bins over [-4,4): width 1/1024. Scores ~N(0,0.41): |s|>4 is ~9.7 sigma,
// clamp bins stay empty; threshold bin (~0.276) is interior.
__device__ __forceinline__ int score_bin(float v) {
    int b = __float2int_rd((v + 4.0f) * 1024.0f);
    return min(max(b, 0), NBINS - 1);
}

// ---------------- K0: zero per-launch state ----------------
__global__ void zero_kernel() {
    int i = blockIdx.x * blockDim.x + threadIdx.x;
    if (i < NH * NBINS) g_hist[i] = 0;
    if (i < NH) g_cnt[i] = 0;
}

// ---------------- double-buffered fp32 GEMM mainloop ----------------
template<int KTOT, bool BT>
__device__ __forceinline__ void gemm_mainloop(
    const float* __restrict__ A, int lda,
    const float* __restrict__ Bm, int ldb,
    int bm, int bn, float acc[TM][TN])
{
    __shared__ float As[2][BK][BM];
    __shared__ float Bs[2][BK][BN];
    const int tid = threadIdx.x;
    const int tr = (tid >> 4) * TM;
    const int tc = (tid & 15) * TN;

    const int ar0 = tid >> 2;           // 0..63
    const int ar1 = ar0 + 64;           // 64..127
    const int ac  = (tid & 3) * 4;      // 0,4,8,12
    const int br0 = tid >> 5;           // 0..7
    const int br1 = br0 + 8;
    const int bc  = (tid & 31) * 4;

    float4 pa0, pa1, pb0, pb1;

    auto loadT = [&](int k0) {
        pa0 = *(const float4*)&A[(size_t)(bm + ar0) * lda + k0 + ac];
        pa1 = *(const float4*)&A[(size_t)(bm + ar1) * lda + k0 + ac];
        if (BT) {
            pb0 = *(const float4*)&Bm[(size_t)(bn + ar0) * ldb + k0 + ac];
            pb1 = *(const float4*)&Bm[(size_t)(bn + ar1) * ldb + k0 + ac];
        } else {
            pb0 = *(const float4*)&Bm[(size_t)(k0 + br0) * ldb + bn + bc];
            pb1 = *(const float4*)&Bm[(size_t)(k0 + br1) * ldb + bn + bc];
        }
    };
    auto storeT = [&](int buf) {
        As[buf][ac + 0][ar0] = pa0.x; As[buf][ac + 1][ar0] = pa0.y;
        As[buf][ac + 2][ar0] = pa0.z; As[buf][ac + 3][ar0] = pa0.w;
        As[buf][ac + 0][ar1] = pa1.x; As[buf][ac + 1][ar1] = pa1.y;
        As[buf][ac + 2][ar1] = pa1.z; As[buf][ac + 3][ar1] = pa1.w;
        if (BT) {
            Bs[buf][ac + 0][ar0] = pb0.x; Bs[buf][ac + 1][ar0] = pb0.y;
            Bs[buf][ac + 2][ar0] = pb0.z; Bs[buf][ac + 3][ar0] = pb0.w;
            Bs[buf][ac + 0][ar1] = pb1.x; Bs[buf][ac + 1][ar1] = pb1.y;
            Bs[buf][ac + 2][ar1] = pb1.z; Bs[buf][ac + 3][ar1] = pb1.w;
        } else {
            *(float4*)&Bs[buf][br0][bc] = pb0;
            *(float4*)&Bs[buf][br1][bc] = pb1;
        }
    };

    loadT(0);
    storeT(0);
    __syncthreads();
    const int NIT = KTOT / BK;
    for (int it = 0; it < NIT; ++it) {
        int buf = it & 1;
        if (it + 1 < NIT) loadT((it + 1) * BK);
#pragma unroll
        for (int kk = 0; kk < BK; ++kk) {
            float4 a0 = *(const float4*)&As[buf][kk][tr];
            float4 a1 = *(const float4*)&As[buf][kk][tr + 4];
            float4 b0 = *(const float4*)&Bs[buf][kk][tc];
            float4 b1 = *(const float4*)&Bs[buf][kk][tc + 4];
            float af[TM] = {a0.x, a0.y, a0.z, a0.w, a1.x, a1.y, a1.z, a1.w};
            float bf[TN] = {b0.x, b0.y, b0.z, b0.w, b1.x, b1.y, b1.z, b1.w};
#pragma unroll
            for (int i = 0; i < TM; i++)
#pragma unroll
                for (int j = 0; j < TN; j++)
                    acc[i][j] += af[i] * bf[j];
        }
        if (it + 1 < NIT) storeT(buf ^ 1);
        __syncthreads();
    }
}

// ---------------- K1: fused QKV projection ----------------
__global__ __launch_bounds__(256, 2) void qkv_kernel(
    const float* __restrict__ x,
    const float* __restrict__ Wq, const float* __restrict__ bq,
    const float* __restrict__ Wk, const float* __restrict__ bk,
    const float* __restrict__ Wv, const float* __restrict__ bv,
    float* __restrict__ q, float* __restrict__ k, float* __restrict__ v)
{
    const float* W; const float* bias; float* C;
    if (blockIdx.z == 0)      { W = Wq; bias = bq; C = q; }
    else if (blockIdx.z == 1) { W = Wk; bias = bk; C = k; }
    else                      { W = Wv; bias = bv; C = v; }

    int bm = blockIdx.y * BM, bn = blockIdx.x * BN;
    int tid = threadIdx.x;
    int tr = (tid >> 4) * TM, tc = (tid & 15) * TN;
    float acc[TM][TN] = {};
    gemm_mainloop<DD, false>(x, DD, W, DD, bm, bn, acc);
#pragma unroll
    for (int i = 0; i < TM; i++) {
        int row = bm + tr + i;
#pragma unroll
        for (int j = 0; j < TN; j += 4) {
            float4 r;
            r.x = acc[i][j + 0] + bias[bn + tc + j + 0];
            r.y = acc[i][j + 1] + bias[bn + tc + j + 1];
            r.z = acc[i][j + 2] + bias[bn + tc + j + 2];
            r.w = acc[i][j + 3] + bias[bn + tc + j + 3];
            *(float4*)&C[(size_t)row * DD + bn + tc + j] = r;
        }
    }
}

// ---------------- K8: output projection ----------------
__global__ __launch_bounds__(256, 2) void outproj_kernel(
    const float* __restrict__ A, const float* __restrict__ W,
    const float* __restrict__ bias, float* __restrict__ C)
{
    int bm = blockIdx.y * BM, bn = blockIdx.x * BN;
    int tid = threadIdx.x;
    int tr = (tid >> 4) * TM, tc = (tid & 15) * TN;
    float acc[TM][TN] = {};
    gemm_mainloop<DD, false>(A, DD, W, DD, bm, bn, acc);
#pragma unroll
    for (int i = 0; i < TM; i++) {
        int row = bm + tr + i;
#pragma unroll
        for (int j = 0; j < TN; j += 4) {
            float4 r;
            r.x = acc[i][j + 0] + bias[bn + tc + j + 0];
            r.y = acc[i][j + 1] + bias[bn + tc + j + 1];
            r.z = acc[i][j + 2] + bias[bn + tc + j + 2];
            r.w = acc[i][j + 3] + bias[bn + tc + j + 3];
            *(float4*)&C[(size_t)row * DD + bn + tc + j] = r;
        }
    }
}

// ---------------- K2: scores = q_h @ k_h^T * 0.125, fused histogram ----------
__global__ __launch_bounds__(256, 2) void scores_kernel() {
    extern __shared__ unsigned shh[];   // NBINS -> 32 KB dynamic
    int h = blockIdx.z;
    int bm = blockIdx.y * BM, bn = blockIdx.x * BN;
    int tid = threadIdx.x;
    int tr = (tid >> 4) * TM, tc = (tid & 15) * TN;

    for (int i = tid; i < NBINS; i += 256) shh[i] = 0;

    float acc[TM][TN] = {};
    gemm_mainloop<HDIM, true>(g_q + h * HDIM, DD, g_k + h * HDIM, DD, bm, bn, acc);
    // mainloop ends with __syncthreads(): shh zeroing complete.

    float* out = g_scores + (size_t)h * SS * SS;
#pragma unroll
    for (int i = 0; i < TM; i++) {
        size_t row = bm + tr + i;
#pragma unroll
        for (int j = 0; j < TN; j += 4) {
            float4 r;
            r.x = acc[i][j + 0] * 0.125f;
            r.y = acc[i][j + 1] * 0.125f;
            r.z = acc[i][j + 2] * 0.125f;
            r.w = acc[i][j + 3] * 0.125f;
            *(float4*)&out[row * SS + bn + tc + j] = r;
            atomicAdd(&shh[score_bin(r.x)], 1u);
            atomicAdd(&shh[score_bin(r.y)], 1u);
            atomicAdd(&shh[score_bin(r.z)], 1u);
            atomicAdd(&shh[score_bin(r.w)], 1u);
        }
    }
    __syncthreads();
    unsigned* gh = g_hist + h * NBINS;
    for (int i = tid; i < NBINS; i += 256) {
        unsigned c = shh[i];
        if (c) atomicAdd(&gh[i], c);
    }
}

// ---------------- inline rank-scan over g_hist -------------------------------
__device__ __forceinline__ void rank_scan_256(
    const unsigned* __restrict__ hh, int tid,
    unsigned* wsum /*[8] shared*/, int* sb0, int* sb1, int* sbase)
{
    const int PER = NBINS / 256;   // 32
    int start = tid * PER;
    unsigned s = 0;
#pragma unroll
    for (int i = 0; i < PER; i++) s += hh[start + i];
    unsigned x = s;
#pragma unroll
    for (int o = 1; o < 32; o <<= 1) {
        unsigned y = __shfl_up_sync(0xffffffffu, x, o);
        if ((tid & 31) >= o) x += y;
    }
    if ((tid & 31) == 31) wsum[tid >> 5] = x;
    __syncthreads();
    if (tid == 0) {
        unsigned c = 0;
        for (int w = 0; w < 8; w++) { unsigned t2 = wsum[w]; wsum[w] = c; c += t2; }
    }
    __syncthreads();
    unsigned c = x - s + wsum[tid >> 5];
    const unsigned I0 = RANK0, I1 = RANK0 + 1;
    for (int i = 0; i < PER; i++) {
        unsigned cnt = hh[start + i];
        if (cnt) {
            if (I0 >= c && I0 < c + cnt) { *sb0 = start + i; *sbase = (int)c; }
            if (I1 >= c && I1 < c + cnt) { *sb1 = start + i; }
        }
        c += cnt;
    }
}

// ---------------- K5: compact candidates (float-interval test, MLP-4) --------
// Predicate equivalence: bin(v) in [B0,B1]  <=>  fl(v+4) in [B0/1024,(B1+1)/1024)
// (monotone bin map; x1024 exact; bounds are exact fp32 constants). Candidate
// set is bit-identical to the bin-index test.
__global__ __launch_bounds__(1024) void compact_kernel() {
    __shared__ unsigned wsum[8];
    __shared__ int sb0, sb1, sbase;
    int h = blockIdx.y;
    int tid = threadIdx.x;
    if (tid < 256) rank_scan_256(g_hist + h * NBINS, tid, wsum, &sb0, &sb1, &sbase);
    else { __syncthreads(); __syncthreads(); }   // match barriers inside
    __syncthreads();
    const float c0 = (float)sb0 * 0.0009765625f;        // B0 / 1024 (exact)
    const float c1 = (float)(sb1 + 1) * 0.0009765625f;  // (B1+1) / 1024 (exact)

    const size_t per_head = (size_t)SS * SS;
    const float4* base = (const float4*)(g_scores + (size_t)h * per_head);
    const size_t n4 = per_head / 4;                     // 1048576
    const size_t stride = (size_t)gridDim.x * blockDim.x;   // 32768
    size_t idx = (size_t)blockIdx.x * blockDim.x + tid;

    auto proc = [&](float4 v) {
#pragma unroll
        for (int t = 0; t < 4; t++) {
            float val = (&v.x)[t];
            float s4 = val + 4.0f;
            if (s4 >= c0 && s4 < c1) {
                int p = atomicAdd(&g_cnt[h], 1);
                if (p < CCAP) g_cand[h * CCAP + p] = val;
            }
        }
    };
    // n4 / stride = 32, divisible by 4: no bounds checks needed.
    for (size_t i = idx; i < n4; i += 4 * stride) {
        float4 v0 = __ldcs(&base[i]);
        float4 v1 = __ldcs(&base[i + stride]);
        float4 v2 = __ldcs(&base[i + 2 * stride]);
        float4 v3 = __ldcs(&base[i + 3 * stride]);
        proc(v0); proc(v1); proc(v2); proc(v3);
    }
}

// ---------------- K6: sort candidates, exact quantile ------------------------
__global__ __launch_bounds__(1024) void select_kernel() {
    extern __shared__ float sm[];
    __shared__ unsigned wsum[8];
    __shared__ int sb0, sb1, sbase;
    int h = blockIdx.x;
    int tid = threadIdx.x;
    if (tid < 256) rank_scan_256(g_hist + h * NBINS, tid, wsum, &sb0, &sb1, &sbase);
    else { __syncthreads(); __syncthreads(); }
    __syncthreads();

    int n = min(g_cnt[h], CCAP);
    int m = 1024;
    while (m < n) m <<= 1;
    for (int i = tid; i < m; i += blockDim.x)
        sm[i] = (i < n) ? g_cand[h * CCAP + i] : inf_f();
    __syncthreads();
    for (int k = 2; k <= m; k <<= 1) {
        for (int j = k >> 1; j > 0; j >>= 1) {
            for (int i = tid; i < m; i += blockDim.x) {
                int ixj = i ^ j;
                if (ixj > i) {
                    bool up = ((i & k) == 0);
                    float a = sm[i], b = sm[ixj];
                    if ((a > b) == up) { sm[i] = b; sm[ixj] = a; }
                }
            }
            __syncthreads();
        }
    }
    if (tid == 0) {
        float idxf = 0.95f * (float)(SS * SS - 1);
        float frac = idxf - floorf(idxf);   // 0.75 in fp32
        int r0 = RANK0 - sbase;
        if (r0 < 0) r0 = 0;
        if (r0 > n - 2) r0 = n - 2;
        float v0 = sm[r0], v1 = sm[r0 + 1];
        g_thr[h] = v0 + frac * (v1 - v0);
    }
}

// ---------------- K7: masked softmax + attn@V, chunked compaction ----------------
#define CH 512
__global__ __launch_bounds__(256) void attn_kernel() {
    __shared__ float          sv[8][CH];
    __shared__ unsigned short si[8][CH];
    int h = blockIdx.y;
    int warp = threadIdx.x >> 5;
    int lane = threadIdx.x & 31;
    int row = blockIdx.x * 8 + warp;
    float t = g_thr[h];
    const float* srow = g_scores + ((size_t)h * SS + row) * SS;
    const float* vh = g_v + h * HDIM;
    const float NEG = -inf_f();
    float m = NEG, l = 0.f, acc0 = 0.f, acc1 = 0.f;
    for (int c0 = 0; c0 < SS; c0 += CH) {
        int cnt = 0;
        float lmax = NEG;
#pragma unroll
        for (int cc = 0; cc < CH; cc += 32) {
            float s = __ldcs(&srow[c0 + cc + lane]);
            bool kept = (s >= t);
            unsigned bal = __ballot_sync(0xffffffffu, kept);
            if (kept) {
                int pos = cnt + __popc(bal & ((1u << lane) - 1u));
                sv[warp][pos] = s;
                si[warp][pos] = (unsigned short)(c0 + cc + lane);
                lmax = fmaxf(lmax, s);
            }
            cnt += __popc(bal);
        }
        if (cnt == 0) continue;
#pragma unroll
        for (int o = 16; o; o >>= 1) lmax = fmaxf(lmax, __shfl_xor_sync(0xffffffffu, lmax, o));
        if (lmax > m) {
            float corr = (m == NEG) ? 0.f : __expf(m - lmax);
            l *= corr; acc0 *= corr; acc1 *= corr;
            m = lmax;
        }
        __syncwarp();
        for (int i = lane; i < cnt; i += 32)
            sv[warp][i] = __expf(sv[warp][i] - m);
        __syncwarp();
        int i = 0;
        for (; i + 4 <= cnt; i += 4) {
            float p0 = sv[warp][i + 0], p1 = sv[warp][i + 1];
            float p2 = sv[warp][i + 2], p3 = sv[warp][i + 3];
            const float* v0 = vh + (size_t)si[warp][i + 0] * DD;
            const float* v1 = vh + (size_t)si[warp][i + 1] * DD;
            const float* v2 = vh + (size_t)si[warp][i + 2] * DD;
            const float* v3 = vh + (size_t)si[warp][i + 3] * DD;
            acc0 += p0 * v0[lane]      + p1 * v1[lane]      + p2 * v2[lane]      + p3 * v3[lane];
            acc1 += p0 * v0[lane + 32] + p1 * v1[lane + 32] + p2 * v2[lane + 32] + p3 * v3[lane + 32];
            l += p0 + p1 + p2 + p3;
        }
        for (; i < cnt; ++i) {
            float p = sv[warp][i];
            const float* vr = vh + (size_t)si[warp][i] * DD;
            acc0 += p * vr[lane];
            acc1 += p * vr[lane + 32];
            l += p;
        }
        __syncwarp();
    }
    float inv = (l > 0.f) ? 1.f / l : 0.f;
    g_o[(size_t)row * DD + h * HDIM + lane]      = acc0 * inv;
    g_o[(size_t)row * DD + h * HDIM + lane + 32] = acc1 * inv;
}

// ---------------- launch ----------------
extern "C" void kernel_launch(void* const* d_in, const int* in_sizes, int n_in,
                              void* d_out, int out_size) {
    (void)in_sizes; (void)n_in; (void)out_size;
    const float* x  = (const float*)d_in[0];
    const float* Wq = (const float*)d_in[1];
    const float* bq = (const float*)d_in[2];
    const float* Wk = (const float*)d_in[3];
    const float* bk = (const float*)d_in[4];
    const float* Wv = (const float*)d_in[5];
    const float* bv = (const float*)d_in[6];
    const float* Wo = (const float*)d_in[7];
    const float* bo = (const float*)d_in[8];
    float* out = (float*)d_out;

    cudaFuncSetAttribute(scores_kernel, cudaFuncAttributeMaxDynamicSharedMemorySize, NBINS * 4);
    cudaFuncSetAttribute(select_kernel, cudaFuncAttributeMaxDynamicSharedMemorySize, CCAP * 4);

    float *pq, *pk, *pv, *po;
    cudaGetSymbolAddress((void**)&pq, g_q);
    cudaGetSymbolAddress((void**)&pk, g_k);
    cudaGetSymbolAddress((void**)&pv, g_v);
    cudaGetSymbolAddress((void**)&po, g_o);

    zero_kernel<<<(NH * NBINS + 255) / 256, 256>>>();
    qkv_kernel<<<dim3(DD / BN, SS / BM, 3), 256>>>(x, Wq, bq, Wk, bk, Wv, bv, pq, pk, pv);
    scores_kernel<<<dim3(SS / BN, SS / BM, NH), 256, NBINS * 4>>>();
    compact_kernel<<<dim3(32, NH), 1024>>>();
    select_kernel<<<NH, 1024, CCAP * 4>>>();
    attn_kernel<<<dim3(SS / 8, NH), 256>>>();
    outproj_kernel<<<dim3(DD / BN, SS / BM), 256>>>(po, Wo, bo, out);
}